// round 5
// baseline (speedup 1.0000x reference)
#include <cuda_runtime.h>
#include <cuda_bf16.h>
#include <cstdint>

// Problem constants (fixed by the reference).
#define LSEQ 8192
#define EDIM 256
#define HDIM 256      // per-direction hidden
#define G4   1024     // 4*HDIM gate rows
#define KTAG 10
#define NCTA 8        // CTAs per direction = one cluster
#define UPB  32       // hidden units per CTA
#define TXBYTES (8 * 128)   // 8 bulk copies x 128 bytes per phase (self included)
#define TAG_START 8
#define TAG_STOP  9

// ---------------------------------------------------------------------------
// Scratch (static device globals: allocation-free per harness rules)
// ---------------------------------------------------------------------------
__device__ float g_P[2][LSEQ][G4];      // input projections + biases, per dir
__device__ float g_h[2][LSEQ][HDIM];    // hidden states per position, per dir
__device__ float g_feats[LSEQ][KTAG];   // emission scores

__device__ __forceinline__ float tanh_fast(float x) {
    float y;
    asm("tanh.approx.f32 %0, %1;" : "=f"(y) : "f"(x));
    return y;
}
__device__ __forceinline__ float sig_fast(float x) {
    return 0.5f * tanh_fast(0.5f * x) + 0.5f;
}
__device__ __forceinline__ uint32_t smem_u32(const void* p) {
    return (uint32_t)__cvta_generic_to_shared(p);
}
__device__ __forceinline__ uint32_t mapa_rank(uint32_t addr, uint32_t rank) {
    uint32_t r;
    asm("mapa.shared::cluster.u32 %0, %1, %2;" : "=r"(r) : "r"(addr), "r"(rank));
    return r;
}
__device__ __forceinline__ void mbar_wait_parity(uint32_t addr, uint32_t parity) {
    asm volatile(
        "{\n\t"
        ".reg .pred P;\n\t"
        "WLOOP%=:\n\t"
        "mbarrier.try_wait.parity.acquire.cluster.shared::cta.b64 P, [%0], %1;\n\t"
        "@!P bra WLOOP%=;\n\t"
        "}"
        :: "r"(addr), "r"(parity) : "memory");
}

// ---------------------------------------------------------------------------
// Input projection GEMM with fused embedding gather:
//   P[dir][m][n] = sum_k emb[sent[m]][k] * Wih[dir][n][k] + bih[n] + bhh[n]
// ---------------------------------------------------------------------------
__global__ __launch_bounds__(256) void proj_kernel(
    const int* __restrict__ sent, const float* __restrict__ emb,
    const float* __restrict__ Wf, const float* __restrict__ bfa, const float* __restrict__ bfb,
    const float* __restrict__ Wb, const float* __restrict__ bba, const float* __restrict__ bbb)
{
    const int dir = blockIdx.z;
    const float* W  = dir ? Wb  : Wf;
    const float* b1 = dir ? bba : bfa;
    const float* b2 = dir ? bbb : bfb;
    float* P = &g_P[dir][0][0];

    __shared__ float As[32][72];
    __shared__ float Bs[32][72];

    const int tid = threadIdx.x;
    const int tx = tid & 15, ty = tid >> 4;
    const int m0 = blockIdx.x * 64, n0 = blockIdx.y * 64;

    float acc[4][4];
#pragma unroll
    for (int i = 0; i < 4; i++)
#pragma unroll
        for (int j = 0; j < 4; j++) acc[i][j] = 0.f;

    for (int kb = 0; kb < EDIM; kb += 32) {
#pragma unroll
        for (int i = 0; i < 2; i++) {
            int slot = tid + i * 256;
            int ml = slot >> 3, k4 = slot & 7;
            int row = sent[m0 + ml];
            float4 av = *reinterpret_cast<const float4*>(&emb[row * EDIM + kb + k4 * 4]);
            As[k4 * 4 + 0][ml] = av.x; As[k4 * 4 + 1][ml] = av.y;
            As[k4 * 4 + 2][ml] = av.z; As[k4 * 4 + 3][ml] = av.w;
            float4 wv = *reinterpret_cast<const float4*>(&W[(n0 + ml) * EDIM + kb + k4 * 4]);
            Bs[k4 * 4 + 0][ml] = wv.x; Bs[k4 * 4 + 1][ml] = wv.y;
            Bs[k4 * 4 + 2][ml] = wv.z; Bs[k4 * 4 + 3][ml] = wv.w;
        }
        __syncthreads();
#pragma unroll
        for (int kk = 0; kk < 32; kk++) {
            float4 a = *reinterpret_cast<const float4*>(&As[kk][ty * 4]);
            float4 b = *reinterpret_cast<const float4*>(&Bs[kk][tx * 4]);
            float av[4] = {a.x, a.y, a.z, a.w};
            float bv[4] = {b.x, b.y, b.z, b.w};
#pragma unroll
            for (int i = 0; i < 4; i++)
#pragma unroll
                for (int j = 0; j < 4; j++) acc[i][j] += av[i] * bv[j];
        }
        __syncthreads();
    }

    float bsum[4];
#pragma unroll
    for (int j = 0; j < 4; j++) bsum[j] = b1[n0 + tx * 4 + j] + b2[n0 + tx * 4 + j];
#pragma unroll
    for (int i = 0; i < 4; i++) {
        float4 o;
        o.x = acc[i][0] + bsum[0]; o.y = acc[i][1] + bsum[1];
        o.z = acc[i][2] + bsum[2]; o.w = acc[i][3] + bsum[3];
        *reinterpret_cast<float4*>(&P[(m0 + ty * 4 + i) * G4 + n0 + tx * 4]) = o;
    }
}

// ---------------------------------------------------------------------------
// Persistent LSTM recurrence over DSMEM with bulk h-exchange.
// Grid = 16 CTAs, cluster 8: CTAs 0-7 = dir 0, CTAs 8-15 = dir 1.
// CTA rank owns units [rank*32, rank*32+32) = 128 gate rows; 512 threads.
// Thread tid = u*16 + g*4 + c: unit u, gate g, column-quarter c; 64 weight
// floats per thread held as 32 packed f32x2 registers.
// h exchange: warp 0 computes h into double-buffered hloc[2][32], then lanes
// 0..7 issue cp.async.bulk (128 B) to all 8 cluster CTAs (self included);
// each bulk completion tx-counts on the destination's mbarrier. Only 8 tx
// events + 1 arrive per barrier phase (vs 112 scalar st.async before).
// ---------------------------------------------------------------------------
__global__ void __cluster_dims__(NCTA, 1, 1) __launch_bounds__(512, 1)
lstm_kernel(const float* __restrict__ Whh_f, const float* __restrict__ Whh_b)
{
    const int dir = blockIdx.x >> 3;
    uint32_t myrank;
    asm("mov.u32 %0, %%cluster_ctarank;" : "=r"(myrank));
    const float* __restrict__ Whh = dir ? Whh_b : Whh_f;
    const float* __restrict__ P = &g_P[dir][0][0];
    float* __restrict__ hs = &g_h[dir][0][0];

    const int tid = threadIdx.x;
    const int u = tid >> 4, g = (tid >> 2) & 3, c = tid & 3;
    const int j0 = (int)myrank * UPB;
    const int r = g * 256 + j0 + u;          // gate row in [0,1024)

    // Weights for row r, cols [c*64, c*64+64), chunk-rotated by (kq+c)&15 so
    // the matching smem 16B reads are bank-conflict-free. Packed as f32x2.
    unsigned long long w2[32];
    {
        const ulonglong2* wrow = reinterpret_cast<const ulonglong2*>(Whh + (size_t)r * HDIM + c * 64);
#pragma unroll
        for (int kq = 0; kq < 16; kq++) {
            int ch = (kq + c) & 15;
            ulonglong2 t = wrow[ch];
            w2[2 * kq + 0] = t.x;
            w2[2 * kq + 1] = t.y;
        }
    }

    __shared__ __align__(16) float sh[2][HDIM];     // assembled h, double buffer
    __shared__ __align__(16) float hloc[2][UPB];    // local h staging (bulk src)
    __shared__ __align__(16) float4 sgate[UPB];
    __shared__ __align__(8) unsigned long long mbar[2];

    const uint32_t mb0 = smem_u32(&mbar[0]);
    const uint32_t mb1 = smem_u32(&mbar[1]);

    if (tid == 0) {
        asm volatile("mbarrier.inval.shared.b64 [%0];" :: "r"(mb0) : "memory");
        asm volatile("mbarrier.inval.shared.b64 [%0];" :: "r"(mb1) : "memory");
        asm volatile("mbarrier.init.shared.b64 [%0], 1;" :: "r"(mb0) : "memory");
        asm volatile("mbarrier.init.shared.b64 [%0], 1;" :: "r"(mb1) : "memory");
        // Pre-post expected tx for h[0] (buf0) and h[1] (buf1): safe, peers
        // only start storing after the cluster sync below.
        asm volatile("mbarrier.arrive.expect_tx.shared.b64 _, [%0], %1;"
                     :: "r"(mb0), "r"((uint32_t)TXBYTES) : "memory");
        asm volatile("mbarrier.arrive.expect_tx.shared.b64 _, [%0], %1;"
                     :: "r"(mb1), "r"((uint32_t)TXBYTES) : "memory");
    }

    // Bulk-copy issuers: lanes 0..7 of warp 0, dst rank = (myrank + lane) & 7
    // (lane 0 = self). Destination region = MY unit slice in the peer's sh.
    uint32_t d_sh0 = 0, d_sh1 = 0, d_mb0 = 0, d_mb1 = 0;
    const uint32_t src_h0 = smem_u32(&hloc[0][0]);
    const uint32_t src_h1 = smem_u32(&hloc[1][0]);
    if (tid < 8) {
        uint32_t dst = (myrank + (uint32_t)tid) & 7;
        d_sh0 = mapa_rank(smem_u32(&sh[0][j0]), dst);
        d_sh1 = mapa_rank(smem_u32(&sh[1][j0]), dst);
        d_mb0 = mapa_rank(mb0, dst);
        d_mb1 = mapa_rank(mb1, dst);
    }

    __syncthreads();
    asm volatile("barrier.cluster.arrive.aligned;" ::: "memory");
    asm volatile("barrier.cluster.wait.aligned;" ::: "memory");

    float creg = 0.f;   // cell state, warp 0 lanes (unit = tid)

    // Deep prefetch of the input projection: pv holds P for step s.
    float pv = 0.f;
    if (c == 0) {
        const int pos0 = dir ? (LSEQ - 1) : 0;
        pv = __ldg(&P[(size_t)pos0 * G4 + r]);
    }

    for (int s = 0; s < LSEQ; s++) {
        const int pos = dir ? (LSEQ - 1 - s) : s;
        const int b = s & 1;

        // Issue next step's P load a full step early (latency fully hidden).
        float pvN = 0.f;
        if (c == 0 && s + 1 < LSEQ) {
            const int posN = dir ? (pos - 1) : (pos + 1);
            pvN = __ldg(&P[(size_t)posN * G4 + r]);
        }

        float part = 0.f;
        if (s > 0) {
            const int pb = (s - 1) & 1;
            const uint32_t parity = (uint32_t)((s - 1) >> 1) & 1u;
            mbar_wait_parity(pb ? mb1 : mb0, parity);

            // Re-post expected tx for h[s+1] on the barrier whose h[s-1]
            // phase just completed (causally precedes any store of h[s+1]).
            if (tid == 0 && s + 1 < LSEQ) {
                asm volatile("mbarrier.arrive.expect_tx.shared.b64 _, [%0], %1;"
                             :: "r"(pb ? mb1 : mb0), "r"((uint32_t)TXBYTES) : "memory");
            }

            // Recurrent partial dot: 16 x 16B LDS + 32 packed f32x2 FMA.
            unsigned long long accA = 0ull, accB = 0ull;
            const ulonglong2* sh2 = reinterpret_cast<const ulonglong2*>(&sh[pb][c * 64]);
#pragma unroll
            for (int kq = 0; kq < 16; kq++) {
                int ch = (kq + c) & 15;
                ulonglong2 hv = sh2[ch];
                asm("fma.rn.f32x2 %0, %1, %2, %0;" : "+l"(accA) : "l"(w2[2 * kq + 0]), "l"(hv.x));
                asm("fma.rn.f32x2 %0, %1, %2, %0;" : "+l"(accB) : "l"(w2[2 * kq + 1]), "l"(hv.y));
            }
            unsigned long long accT;
            asm("add.rn.f32x2 %0, %1, %2;" : "=l"(accT) : "l"(accA), "l"(accB));
            part = __uint_as_float((uint32_t)accT) + __uint_as_float((uint32_t)(accT >> 32));
        }

        // Reduce across the 4 column-quarters (contiguous lanes).
        part += __shfl_down_sync(0xFFFFFFFFu, part, 2, 4);
        part += __shfl_down_sync(0xFFFFFFFFu, part, 1, 4);
        if (c == 0) reinterpret_cast<float*>(sgate)[u * 4 + g] = part + pv;
        pv = pvN;
        __syncthreads();   // the ONLY block-wide barrier per step

        // Warp 0: cell/hidden update, stage h, broadcast via 8 bulk copies.
        if (tid < UPB) {
            float4 gt = sgate[tid];
            creg = sig_fast(gt.y) * creg + sig_fast(gt.x) * tanh_fast(gt.z);
            float hv = sig_fast(gt.w) * tanh_fast(creg);
            hloc[b][tid] = hv;
            hs[(size_t)pos * HDIM + j0 + tid] = hv;   // for feats (off-path)
            __syncwarp();
            if (tid < 8) {
                asm volatile("fence.proxy.async.shared::cta;" ::: "memory");
                asm volatile(
                    "cp.async.bulk.shared::cluster.shared::cta.mbarrier::complete_tx::bytes "
                    "[%0], [%1], %2, [%3];"
                    :: "r"(b ? d_sh1 : d_sh0),
                       "r"(b ? src_h1 : src_h0),
                       "r"((uint32_t)(UPB * 4)),
                       "r"(b ? d_mb1 : d_mb0)
                    : "memory");
            }
        }
    }

    // Keep the cluster resident until all outgoing bulk traffic has landed.
    asm volatile("barrier.cluster.arrive.aligned;" ::: "memory");
    asm volatile("barrier.cluster.wait.aligned;" ::: "memory");
}

// ---------------------------------------------------------------------------
// feats[t][k] = [hf[t], hb[t]] . W_tag[k] + b_tag[k]
// ---------------------------------------------------------------------------
__global__ __launch_bounds__(64) void feats_kernel(
    const float* __restrict__ Wtag, const float* __restrict__ btag)
{
    __shared__ float shc[512];
    const int t = blockIdx.x;
    const int tid = threadIdx.x;
#pragma unroll
    for (int i = 0; i < 8; i++) {
        int d = tid + 64 * i;
        shc[d] = (d < HDIM) ? g_h[0][t][d] : g_h[1][t][d - HDIM];
    }
    __syncthreads();
    const int wr = tid >> 5, l = tid & 31;
#pragma unroll
    for (int kk = 0; kk < 5; kk++) {
        int k = wr * 5 + kk;
        float ssum = 0.f;
#pragma unroll
        for (int j = 0; j < 16; j++) {
            int d = l + 32 * j;
            ssum += shc[d] * Wtag[k * 512 + d];
        }
#pragma unroll
        for (int off = 16; off >= 1; off >>= 1)
            ssum += __shfl_down_sync(0xFFFFFFFFu, ssum, off);
        if (l == 0) g_feats[t][k] = ssum + btag[k];
    }
}

// ---------------------------------------------------------------------------
// Viterbi max-plus scan + traceback. One warp; backpointers in dynamic smem.
// First-max argmax via a left-priority '>=' tree (depth 4) == jnp.argmax.
// ---------------------------------------------------------------------------
struct VK { float v; int i; };
__device__ __forceinline__ VK vk_cmb(VK a, VK b) {   // a carries lower indices
    VK r; r.v = (a.v >= b.v) ? a.v : b.v; r.i = (a.v >= b.v) ? a.i : b.i; return r;
}

__global__ void viterbi_kernel(const float* __restrict__ trans,
                               float* __restrict__ out, int out_size)
{
    extern __shared__ unsigned char bp[];   // [LSEQ][KTAG]
    const int lane = threadIdx.x;
    const int j = lane < KTAG ? lane : KTAG - 1;

    float Trow[KTAG];
#pragma unroll
    for (int p = 0; p < KTAG; p++) Trow[p] = trans[j * KTAG + p];

    float v = (lane == TAG_START) ? 0.f : -10000.f;
    float fc = g_feats[0][j];

    for (int t = 0; t < LSEQ; t++) {
        float fn = (t + 1 < LSEQ) ? g_feats[t + 1][j] : 0.f;   // prefetch

        VK e[KTAG];
#pragma unroll
        for (int p = 0; p < KTAG; p++) {
            float vp = __shfl_sync(0xFFFFFFFFu, v, p);
            e[p].v = vp + Trow[p]; e[p].i = p;
        }
        VK m01 = vk_cmb(e[0], e[1]), m23 = vk_cmb(e[2], e[3]);
        VK m45 = vk_cmb(e[4], e[5]), m67 = vk_cmb(e[6], e[7]);
        VK m89 = vk_cmb(e[8], e[9]);
        VK mA = vk_cmb(m01, m23), mB = vk_cmb(m45, m67);
        VK best = vk_cmb(vk_cmb(mA, mB), m89);

        if (lane < KTAG) bp[t * KTAG + lane] = (unsigned char)best.i;
        v = best.v + fc;
        fc = fn;
    }

    float term = v + trans[TAG_STOP * KTAG + j];
    VK e[KTAG];
#pragma unroll
    for (int p = 0; p < KTAG; p++) {
        e[p].v = __shfl_sync(0xFFFFFFFFu, term, p); e[p].i = p;
    }
    VK m01 = vk_cmb(e[0], e[1]), m23 = vk_cmb(e[2], e[3]);
    VK m45 = vk_cmb(e[4], e[5]), m67 = vk_cmb(e[6], e[7]);
    VK m89 = vk_cmb(e[8], e[9]);
    VK best = vk_cmb(vk_cmb(vk_cmb(m01, m23), vk_cmb(m45, m67)), m89);
    __syncwarp();

    if (lane == 0) {
        if (out_size > 0) out[0] = best.v;                // score
        int tag = best.i;
        if (out_size > LSEQ) out[LSEQ] = (float)tag;      // path[L-1]
        for (int t = LSEQ - 1; t >= 1; t--) {
            tag = bp[t * KTAG + tag];
            if (out_size > t) out[t] = (float)tag;        // path[t-1] at index t
        }
    }
}

// ---------------------------------------------------------------------------
// Launch
// ---------------------------------------------------------------------------
extern "C" void kernel_launch(void* const* d_in, const int* in_sizes, int n_in,
                              void* d_out, int out_size)
{
    const int*   sent  = (const int*)  d_in[0];
    const float* emb   = (const float*)d_in[1];
    const float* Wih_f = (const float*)d_in[2];
    const float* Whh_f = (const float*)d_in[3];
    const float* bih_f = (const float*)d_in[4];
    const float* bhh_f = (const float*)d_in[5];
    const float* Wih_b = (const float*)d_in[6];
    const float* Whh_b = (const float*)d_in[7];
    const float* bih_b = (const float*)d_in[8];
    const float* bhh_b = (const float*)d_in[9];
    const float* W_tag = (const float*)d_in[10];
    const float* b_tag = (const float*)d_in[11];
    const float* trans = (const float*)d_in[12];
    float* out = (float*)d_out;

    cudaFuncSetAttribute(viterbi_kernel,
                         cudaFuncAttributeMaxDynamicSharedMemorySize,
                         LSEQ * KTAG);

    proj_kernel<<<dim3(LSEQ / 64, G4 / 64, 2), 256>>>(
        sent, emb, Wih_f, bih_f, bhh_f, Wih_b, bih_b, bhh_b);
    lstm_kernel<<<2 * NCTA, 512>>>(Whh_f, Whh_b);
    feats_kernel<<<LSEQ, 64>>>(W_tag, b_tag);
    viterbi_kernel<<<1, 32, LSEQ * KTAG>>>(trans, out, out_size);
}

// round 6
// speedup vs baseline: 1.1277x; 1.1277x over previous
#include <cuda_runtime.h>
#include <cuda_bf16.h>
#include <cstdint>

// Problem constants (fixed by the reference).
#define LSEQ 8192
#define EDIM 256
#define HDIM 256      // per-direction hidden
#define G4   1024     // 4*HDIM gate rows
#define KTAG 10
#define NCTA 8        // CTAs per direction = one cluster
#define UPB  32       // hidden units per CTA
#define TXBYTES (8 * 128)   // 8 source CTAs x 128 bytes each per phase (self incl)
#define TAG_START 8
#define TAG_STOP  9

// ---------------------------------------------------------------------------
// Scratch (static device globals: allocation-free per harness rules)
// ---------------------------------------------------------------------------
__device__ float g_P[2][LSEQ][G4];      // input projections + biases, per dir
__device__ float g_h[2][LSEQ][HDIM];    // hidden states per position, per dir
__device__ float g_feats[LSEQ][KTAG];   // emission scores

__device__ __forceinline__ float tanh_fast(float x) {
    float y;
    asm("tanh.approx.f32 %0, %1;" : "=f"(y) : "f"(x));
    return y;
}
__device__ __forceinline__ float sig_fast(float x) {
    return 0.5f * tanh_fast(0.5f * x) + 0.5f;
}
__device__ __forceinline__ uint32_t smem_u32(const void* p) {
    return (uint32_t)__cvta_generic_to_shared(p);
}
__device__ __forceinline__ uint32_t mapa_rank(uint32_t addr, uint32_t rank) {
    uint32_t r;
    asm("mapa.shared::cluster.u32 %0, %1, %2;" : "=r"(r) : "r"(addr), "r"(rank));
    return r;
}
__device__ __forceinline__ void mbar_wait_parity(uint32_t addr, uint32_t parity) {
    asm volatile(
        "{\n\t"
        ".reg .pred P;\n\t"
        "WLOOP%=:\n\t"
        "mbarrier.try_wait.parity.acquire.cluster.shared::cta.b64 P, [%0], %1;\n\t"
        "@!P bra WLOOP%=;\n\t"
        "}"
        :: "r"(addr), "r"(parity) : "memory");
}

// ---------------------------------------------------------------------------
// Input projection GEMM with fused embedding gather:
//   P[dir][m][n] = sum_k emb[sent[m]][k] * Wih[dir][n][k] + bih[n] + bhh[n]
// Inner product uses packed fma.rn.f32x2 (bit-identical to two FFMA.rn).
// ---------------------------------------------------------------------------
__global__ __launch_bounds__(256) void proj_kernel(
    const int* __restrict__ sent, const float* __restrict__ emb,
    const float* __restrict__ Wf, const float* __restrict__ bfa, const float* __restrict__ bfb,
    const float* __restrict__ Wb, const float* __restrict__ bba, const float* __restrict__ bbb)
{
    const int dir = blockIdx.z;
    const float* W  = dir ? Wb  : Wf;
    const float* b1 = dir ? bba : bfa;
    const float* b2 = dir ? bbb : bfb;
    float* P = &g_P[dir][0][0];

    __shared__ float As[32][72];
    __shared__ float Bs[32][72];

    const int tid = threadIdx.x;
    const int tx = tid & 15, ty = tid >> 4;
    const int m0 = blockIdx.x * 64, n0 = blockIdx.y * 64;

    unsigned long long accp[4][2];
#pragma unroll
    for (int i = 0; i < 4; i++) { accp[i][0] = 0ull; accp[i][1] = 0ull; }

    for (int kb = 0; kb < EDIM; kb += 32) {
#pragma unroll
        for (int i = 0; i < 2; i++) {
            int slot = tid + i * 256;
            int ml = slot >> 3, k4 = slot & 7;
            int row = sent[m0 + ml];
            float4 av = *reinterpret_cast<const float4*>(&emb[row * EDIM + kb + k4 * 4]);
            As[k4 * 4 + 0][ml] = av.x; As[k4 * 4 + 1][ml] = av.y;
            As[k4 * 4 + 2][ml] = av.z; As[k4 * 4 + 3][ml] = av.w;
            float4 wv = *reinterpret_cast<const float4*>(&W[(n0 + ml) * EDIM + kb + k4 * 4]);
            Bs[k4 * 4 + 0][ml] = wv.x; Bs[k4 * 4 + 1][ml] = wv.y;
            Bs[k4 * 4 + 2][ml] = wv.z; Bs[k4 * 4 + 3][ml] = wv.w;
        }
        __syncthreads();
#pragma unroll
        for (int kk = 0; kk < 32; kk++) {
            float4 a = *reinterpret_cast<const float4*>(&As[kk][ty * 4]);
            ulonglong2 bq = *reinterpret_cast<const ulonglong2*>(&Bs[kk][tx * 4]);
            float av[4] = {a.x, a.y, a.z, a.w};
#pragma unroll
            for (int i = 0; i < 4; i++) {
                unsigned long long ad;
                asm("mov.b64 %0, {%1, %1};" : "=l"(ad) : "f"(av[i]));
                asm("fma.rn.f32x2 %0, %1, %2, %0;" : "+l"(accp[i][0]) : "l"(ad), "l"(bq.x));
                asm("fma.rn.f32x2 %0, %1, %2, %0;" : "+l"(accp[i][1]) : "l"(ad), "l"(bq.y));
            }
        }
        __syncthreads();
    }

    float bsum[4];
#pragma unroll
    for (int j = 0; j < 4; j++) bsum[j] = b1[n0 + tx * 4 + j] + b2[n0 + tx * 4 + j];
#pragma unroll
    for (int i = 0; i < 4; i++) {
        float4 o;
        o.x = __uint_as_float((uint32_t)accp[i][0])         + bsum[0];
        o.y = __uint_as_float((uint32_t)(accp[i][0] >> 32)) + bsum[1];
        o.z = __uint_as_float((uint32_t)accp[i][1])         + bsum[2];
        o.w = __uint_as_float((uint32_t)(accp[i][1] >> 32)) + bsum[3];
        *reinterpret_cast<float4*>(&P[(m0 + ty * 4 + i) * G4 + n0 + tx * 4]) = o;
    }
}

// ---------------------------------------------------------------------------
// Persistent LSTM recurrence over DSMEM, scalar st.async exchange.
// Grid = 16 CTAs, cluster 8: CTAs 0-7 = dir 0, CTAs 8-15 = dir 1.
// CTA rank owns units [rank*32, rank*32+32) = 128 gate rows; 512 threads.
// Thread tid = u*16 + g*4 + c: unit u, gate g, column-quarter c; 64 weight
// floats per thread held as 32 packed f32x2 registers.
// Per step: ONE __syncthreads; warp 0 reads sgate, computes h, packs pairs
// via shfl, and lanes 0..15 st.async.b64 the CTA's 32 h values to all 8
// ranks (self included). Self-delivery tx-counts on my own barrier, so the
// consumers' mbar wait doubles as the local release/acquire.
// ---------------------------------------------------------------------------
__global__ void __cluster_dims__(NCTA, 1, 1) __launch_bounds__(512, 1)
lstm_kernel(const float* __restrict__ Whh_f, const float* __restrict__ Whh_b)
{
    const int dir = blockIdx.x >> 3;
    uint32_t myrank;
    asm("mov.u32 %0, %%cluster_ctarank;" : "=r"(myrank));
    const float* __restrict__ Whh = dir ? Whh_b : Whh_f;
    const float* __restrict__ P = &g_P[dir][0][0];
    float* __restrict__ hs = &g_h[dir][0][0];

    const int tid = threadIdx.x;
    const int u = tid >> 4, g = (tid >> 2) & 3, c = tid & 3;
    const int j0 = (int)myrank * UPB;
    const int r = g * 256 + j0 + u;          // gate row in [0,1024)

    // Weights for row r, cols [c*64, c*64+64), chunk-rotated by (kq+c)&15 so
    // the matching smem 16B reads are bank-conflict-free. Packed as f32x2.
    unsigned long long w2[32];
    {
        const ulonglong2* wrow = reinterpret_cast<const ulonglong2*>(Whh + (size_t)r * HDIM + c * 64);
#pragma unroll
        for (int kq = 0; kq < 16; kq++) {
            int ch = (kq + c) & 15;
            ulonglong2 t = wrow[ch];
            w2[2 * kq + 0] = t.x;
            w2[2 * kq + 1] = t.y;
        }
    }

    __shared__ __align__(16) float sh[2][HDIM];     // assembled h, double buffer
    __shared__ __align__(16) float4 sgate[UPB];
    __shared__ __align__(8) unsigned long long mbar[2];

    const uint32_t mb0 = smem_u32(&mbar[0]);
    const uint32_t mb1 = smem_u32(&mbar[1]);

    if (tid == 0) {
        asm volatile("mbarrier.inval.shared.b64 [%0];" :: "r"(mb0) : "memory");
        asm volatile("mbarrier.inval.shared.b64 [%0];" :: "r"(mb1) : "memory");
        asm volatile("mbarrier.init.shared.b64 [%0], 1;" :: "r"(mb0) : "memory");
        asm volatile("mbarrier.init.shared.b64 [%0], 1;" :: "r"(mb1) : "memory");
        // Pre-post expected tx for h[0] (buf0) and h[1] (buf1): safe, peers
        // only start storing after the cluster sync below.
        asm volatile("mbarrier.arrive.expect_tx.shared.b64 _, [%0], %1;"
                     :: "r"(mb0), "r"((uint32_t)TXBYTES) : "memory");
        asm volatile("mbarrier.arrive.expect_tx.shared.b64 _, [%0], %1;"
                     :: "r"(mb1), "r"((uint32_t)TXBYTES) : "memory");
    }

    // Local (pre-mapa) addresses for the send targets: my slice in sh[b].
    const uint32_t la0 = smem_u32(&sh[0][j0]);
    const uint32_t la1 = smem_u32(&sh[1][j0]);

    __syncthreads();
    asm volatile("barrier.cluster.arrive.aligned;" ::: "memory");
    asm volatile("barrier.cluster.wait.aligned;" ::: "memory");

    float creg = 0.f;   // cell state, warp 0 lanes (unit = lane)

    // Deep prefetch of the input projection: pv holds P for step s.
    float pv = 0.f;
    if (c == 0) {
        const int pos0 = dir ? (LSEQ - 1) : 0;
        pv = __ldg(&P[(size_t)pos0 * G4 + r]);
    }

    for (int s = 0; s < LSEQ; s++) {
        const int pos = dir ? (LSEQ - 1 - s) : s;
        const int b = s & 1;

        // Issue next step's P load a full step early (latency fully hidden).
        float pvN = 0.f;
        if (c == 0 && s + 1 < LSEQ) {
            const int posN = dir ? (pos - 1) : (pos + 1);
            pvN = __ldg(&P[(size_t)posN * G4 + r]);
        }

        float part = 0.f;
        if (s > 0) {
            const int pb = (s - 1) & 1;
            const uint32_t parity = (uint32_t)((s - 1) >> 1) & 1u;
            mbar_wait_parity(pb ? mb1 : mb0, parity);

            // Re-post expected tx for h[s+1] on the barrier whose h[s-1]
            // phase just completed (causally precedes any store of h[s+1]).
            if (tid == 0 && s + 1 < LSEQ) {
                asm volatile("mbarrier.arrive.expect_tx.shared.b64 _, [%0], %1;"
                             :: "r"(pb ? mb1 : mb0), "r"((uint32_t)TXBYTES) : "memory");
            }

            // Recurrent partial dot: 16 x 16B LDS + 32 packed f32x2 FMA.
            unsigned long long accA = 0ull, accB = 0ull;
            const ulonglong2* sh2 = reinterpret_cast<const ulonglong2*>(&sh[pb][c * 64]);
#pragma unroll
            for (int kq = 0; kq < 16; kq++) {
                int ch = (kq + c) & 15;
                ulonglong2 hv = sh2[ch];
                asm("fma.rn.f32x2 %0, %1, %2, %0;" : "+l"(accA) : "l"(w2[2 * kq + 0]), "l"(hv.x));
                asm("fma.rn.f32x2 %0, %1, %2, %0;" : "+l"(accB) : "l"(w2[2 * kq + 1]), "l"(hv.y));
            }
            unsigned long long accT;
            asm("add.rn.f32x2 %0, %1, %2;" : "=l"(accT) : "l"(accA), "l"(accB));
            part = __uint_as_float((uint32_t)accT) + __uint_as_float((uint32_t)(accT >> 32));
        }

        // Reduce across the 4 column-quarters (contiguous lanes).
        part += __shfl_down_sync(0xFFFFFFFFu, part, 2, 4);
        part += __shfl_down_sync(0xFFFFFFFFu, part, 1, 4);
        if (c == 0) reinterpret_cast<float*>(sgate)[u * 4 + g] = part + pv;
        pv = pvN;
        __syncthreads();   // the ONLY block-wide barrier per step

        // Warp 0: cell/hidden update + register-sourced st.async broadcast.
        if (tid < UPB) {
            float4 gt = sgate[tid];
            creg = sig_fast(gt.y) * creg + sig_fast(gt.x) * tanh_fast(gt.z);
            float hv = sig_fast(gt.w) * tanh_fast(creg);
            hs[(size_t)pos * HDIM + j0 + tid] = hv;   // for feats (off-path)
            // Pack (h[2i], h[2i+1]) into lane i (i < 16).
            float hlo = __shfl_sync(0xFFFFFFFFu, hv, (tid & 15) * 2);
            float hhi = __shfl_sync(0xFFFFFFFFu, hv, (tid & 15) * 2 + 1);
            if (tid < 16 && s + 1 < LSEQ) {
                unsigned long long pk =
                    (unsigned long long)__float_as_uint(hlo) |
                    ((unsigned long long)__float_as_uint(hhi) << 32);
                const uint32_t la = (b ? la1 : la0) + (uint32_t)tid * 8;
                const uint32_t mbb = b ? mb1 : mb0;
#pragma unroll
                for (int p = 0; p < 8; p++) {
                    uint32_t d = (myrank + 1 + (uint32_t)p) & 7;   // self last
                    uint32_t ra = mapa_rank(la, d);
                    uint32_t rm = mapa_rank(mbb, d);
                    asm volatile(
                        "st.async.shared::cluster.mbarrier::complete_tx::bytes.b64 "
                        "[%0], %1, [%2];"
                        :: "r"(ra), "l"(pk), "r"(rm) : "memory");
                }
            }
        }
    }

    // Keep the cluster resident until all outgoing traffic has landed.
    asm volatile("barrier.cluster.arrive.aligned;" ::: "memory");
    asm volatile("barrier.cluster.wait.aligned;" ::: "memory");
}

// ---------------------------------------------------------------------------
// feats[t][k] = [hf[t], hb[t]] . W_tag[k] + b_tag[k]
// ---------------------------------------------------------------------------
__global__ __launch_bounds__(64) void feats_kernel(
    const float* __restrict__ Wtag, const float* __restrict__ btag)
{
    __shared__ float shc[512];
    const int t = blockIdx.x;
    const int tid = threadIdx.x;
#pragma unroll
    for (int i = 0; i < 8; i++) {
        int d = tid + 64 * i;
        shc[d] = (d < HDIM) ? g_h[0][t][d] : g_h[1][t][d - HDIM];
    }
    __syncthreads();
    const int wr = tid >> 5, l = tid & 31;
#pragma unroll
    for (int kk = 0; kk < 5; kk++) {
        int k = wr * 5 + kk;
        float ssum = 0.f;
#pragma unroll
        for (int j = 0; j < 16; j++) {
            int d = l + 32 * j;
            ssum += shc[d] * Wtag[k * 512 + d];
        }
#pragma unroll
        for (int off = 16; off >= 1; off >>= 1)
            ssum += __shfl_down_sync(0xFFFFFFFFu, ssum, off);
        if (l == 0) g_feats[t][k] = ssum + btag[k];
    }
}

// ---------------------------------------------------------------------------
// Viterbi max-plus scan + traceback. One warp; backpointers in dynamic smem.
// First-max argmax via a left-priority '>=' tree (depth 4) == jnp.argmax.
// ---------------------------------------------------------------------------
struct VK { float v; int i; };
__device__ __forceinline__ VK vk_cmb(VK a, VK b) {   // a carries lower indices
    VK r; r.v = (a.v >= b.v) ? a.v : b.v; r.i = (a.v >= b.v) ? a.i : b.i; return r;
}

__global__ void viterbi_kernel(const float* __restrict__ trans,
                               float* __restrict__ out, int out_size)
{
    extern __shared__ unsigned char bp[];   // [LSEQ][KTAG]
    const int lane = threadIdx.x;
    const int j = lane < KTAG ? lane : KTAG - 1;

    float Trow[KTAG];
#pragma unroll
    for (int p = 0; p < KTAG; p++) Trow[p] = trans[j * KTAG + p];

    float v = (lane == TAG_START) ? 0.f : -10000.f;
    float fc = g_feats[0][j];

    for (int t = 0; t < LSEQ; t++) {
        float fn = (t + 1 < LSEQ) ? g_feats[t + 1][j] : 0.f;   // prefetch

        VK e[KTAG];
#pragma unroll
        for (int p = 0; p < KTAG; p++) {
            float vp = __shfl_sync(0xFFFFFFFFu, v, p);
            e[p].v = vp + Trow[p]; e[p].i = p;
        }
        VK m01 = vk_cmb(e[0], e[1]), m23 = vk_cmb(e[2], e[3]);
        VK m45 = vk_cmb(e[4], e[5]), m67 = vk_cmb(e[6], e[7]);
        VK m89 = vk_cmb(e[8], e[9]);
        VK mA = vk_cmb(m01, m23), mB = vk_cmb(m45, m67);
        VK best = vk_cmb(vk_cmb(mA, mB), m89);

        if (lane < KTAG) bp[t * KTAG + lane] = (unsigned char)best.i;
        v = best.v + fc;
        fc = fn;
    }

    float term = v + trans[TAG_STOP * KTAG + j];
    VK e[KTAG];
#pragma unroll
    for (int p = 0; p < KTAG; p++) {
        e[p].v = __shfl_sync(0xFFFFFFFFu, term, p); e[p].i = p;
    }
    VK m01 = vk_cmb(e[0], e[1]), m23 = vk_cmb(e[2], e[3]);
    VK m45 = vk_cmb(e[4], e[5]), m67 = vk_cmb(e[6], e[7]);
    VK m89 = vk_cmb(e[8], e[9]);
    VK best = vk_cmb(vk_cmb(vk_cmb(m01, m23), vk_cmb(m45, m67)), m89);
    __syncwarp();

    if (lane == 0) {
        if (out_size > 0) out[0] = best.v;                // score
        int tag = best.i;
        if (out_size > LSEQ) out[LSEQ] = (float)tag;      // path[L-1]
        for (int t = LSEQ - 1; t >= 1; t--) {
            tag = bp[t * KTAG + tag];
            if (out_size > t) out[t] = (float)tag;        // path[t-1] at index t
        }
    }
}

// ---------------------------------------------------------------------------
// Launch
// ---------------------------------------------------------------------------
extern "C" void kernel_launch(void* const* d_in, const int* in_sizes, int n_in,
                              void* d_out, int out_size)
{
    const int*   sent  = (const int*)  d_in[0];
    const float* emb   = (const float*)d_in[1];
    const float* Wih_f = (const float*)d_in[2];
    const float* Whh_f = (const float*)d_in[3];
    const float* bih_f = (const float*)d_in[4];
    const float* bhh_f = (const float*)d_in[5];
    const float* Wih_b = (const float*)d_in[6];
    const float* Whh_b = (const float*)d_in[7];
    const float* bih_b = (const float*)d_in[8];
    const float* bhh_b = (const float*)d_in[9];
    const float* W_tag = (const float*)d_in[10];
    const float* b_tag = (const float*)d_in[11];
    const float* trans = (const float*)d_in[12];
    float* out = (float*)d_out;

    cudaFuncSetAttribute(viterbi_kernel,
                         cudaFuncAttributeMaxDynamicSharedMemorySize,
                         LSEQ * KTAG);

    proj_kernel<<<dim3(LSEQ / 64, G4 / 64, 2), 256>>>(
        sent, emb, Wih_f, bih_f, bhh_f, Wih_b, bih_b, bhh_b);
    lstm_kernel<<<2 * NCTA, 512>>>(Whh_f, Whh_b);
    feats_kernel<<<LSEQ, 64>>>(W_tag, b_tag);
    viterbi_kernel<<<1, 32, LSEQ * KTAG>>>(trans, out, out_size);
}